// round 14
// baseline (speedup 1.0000x reference)
#include <cuda_runtime.h>
#include <cuda_bf16.h>
#include <cuda_fp16.h>
#include <math.h>
#include <stdint.h>

// ---------------- problem constants ----------------
#define BB 2
#define TT 2048
#define DD 2048
#define HH 8
#define DK 256
#define DV 256
#define NC 32          // T / CHUNK
#define CK 64          // chunk size
#define INTER 2816
#define EPSV 1e-5f
#define NQKVG 8192     // batched projection width

// ---------------- scratch (device globals; no allocations allowed) ----------
#define NTOK (BB*TT)               // 4096
__device__ float g_qkvg[NTOK*NQKVG];   // batched q|k|v|g projections
__device__ float g_q  [NTOK*DD];       // q2 (prescaled)
__device__ float g_k  [NTOK*DD];       // k2 (prescaled)
__device__ float g_v  [NTOK*DD];
__device__ __half g_M [BB*HH*NC*DK*DV];   // fp16 chunk KV summaries
__device__ __half g_S [BB*HH*NC*DK*DV];   // fp16 per-chunk states
__device__ float g_o  [NTOK*DD];
__device__ float g_h  [NTOK*DD];
__device__ float g_gy [NTOK*2*INTER];

// fp16 buffers (A: activations, B: transposed weights)
#define AMAX (NTOK*INTER)
#define BMAX (4*DD*DD)
__device__ __align__(256) __half g_ah[AMAX];
__device__ __align__(256) __half g_bh[BMAX];

// ---------------- f32x2 packed-FMA helpers ----------------
__device__ __forceinline__ unsigned long long pk2(float lo, float hi) {
    unsigned long long r;
    asm("mov.b64 %0, {%1, %2};" : "=l"(r) : "f"(lo), "f"(hi));
    return r;
}
__device__ __forceinline__ void fma2(unsigned long long& c, unsigned long long a, unsigned long long b) {
    asm("fma.rn.f32x2 %0, %1, %2, %0;" : "+l"(c) : "l"(a), "l"(b));
}
__device__ __forceinline__ float2 up2(unsigned long long v) {
    float2 r;
    asm("mov.b64 {%0, %1}, %2;" : "=f"(r.x), "=f"(r.y) : "l"(v));
    return r;
}

__device__ __forceinline__ float sigf(float x) { return 1.0f / (1.0f + expf(-x)); }

__device__ __forceinline__ float block_sum_256(float v) {
    __shared__ float red[8];
    __shared__ float tot;
    #pragma unroll
    for (int o = 16; o; o >>= 1) v += __shfl_xor_sync(0xffffffffu, v, o);
    int tid = threadIdx.x;
    if ((tid & 31) == 0) red[tid >> 5] = v;
    __syncthreads();
    if (tid == 0) {
        float t = red[0];
        #pragma unroll
        for (int i = 1; i < 8; i++) t += red[i];
        tot = t;
    }
    __syncthreads();
    return tot;
}

// ================= baseline-PTX MMA helpers =================
__device__ __forceinline__ uint32_t smem_u32(const void* p) {
    uint32_t a;
    asm("{ .reg .u64 t; cvta.to.shared.u64 t, %1; cvt.u32.u64 %0, t; }" : "=r"(a) : "l"(p));
    return a;
}
#define SWZ64(off) ((off) ^ ((((unsigned)(off)) >> 3) & 0x30u))

__device__ __forceinline__ void ldsm4(uint32_t* r, uint32_t addr) {
    asm volatile("ldmatrix.sync.aligned.m8n8.x4.shared.b16 {%0,%1,%2,%3}, [%4];"
                 : "=r"(r[0]), "=r"(r[1]), "=r"(r[2]), "=r"(r[3]) : "r"(addr));
}
__device__ __forceinline__ void mma16816(float* d, const uint32_t* a, const uint32_t* b) {
    asm volatile(
        "mma.sync.aligned.m16n8k16.row.col.f32.f16.f16.f32 "
        "{%0,%1,%2,%3}, {%4,%5,%6,%7}, {%8,%9}, {%0,%1,%2,%3};"
        : "+f"(d[0]), "+f"(d[1]), "+f"(d[2]), "+f"(d[3])
        : "r"(a[0]), "r"(a[1]), "r"(a[2]), "r"(a[3]), "r"(b[0]), "r"(b[1]));
}
__device__ __forceinline__ void cpasync16(uint32_t dst, const void* src) {
    asm volatile("cp.async.cg.shared.global [%0], [%1], 16;" :: "r"(dst), "l"(src));
}

// ================= conversion / fused elementwise kernels =================

__global__ void __launch_bounds__(256) rmsnorm_half_kernel(const float* __restrict__ in,
                                                           const float* __restrict__ w,
                                                           __half* __restrict__ hi) {
    const size_t base = (size_t)blockIdx.x * DD;
    const int tid = threadIdx.x;
    float4 v0 = *(const float4*)(in + base + tid * 4);
    float4 v1 = *(const float4*)(in + base + 1024 + tid * 4);
    float ss = v0.x*v0.x + v0.y*v0.y + v0.z*v0.z + v0.w*v0.w
             + v1.x*v1.x + v1.y*v1.y + v1.z*v1.z + v1.w*v1.w;
    float tot = block_sum_256(ss);
    float rinv = rsqrtf(tot * (1.0f / (float)DD) + EPSV);
    float4 w0 = *(const float4*)(w + tid * 4);
    float4 w1 = *(const float4*)(w + 1024 + tid * 4);
    size_t o0 = base + tid * 4, o1 = base + 1024 + tid * 4;
    *(__half2*)(hi + o0)     = __half2{__float2half_rn(v0.x*rinv*w0.x), __float2half_rn(v0.y*rinv*w0.y)};
    *(__half2*)(hi + o0 + 2) = __half2{__float2half_rn(v0.z*rinv*w0.z), __float2half_rn(v0.w*rinv*w0.w)};
    *(__half2*)(hi + o1)     = __half2{__float2half_rn(v1.x*rinv*w1.x), __float2half_rn(v1.y*rinv*w1.y)};
    *(__half2*)(hi + o1 + 2) = __half2{__float2half_rn(v1.z*rinv*w1.z), __float2half_rn(v1.w*rinv*w1.w)};
}

// W[K][N] fp32 -> Bt[N][K] fp16 (transpose). 32x32 tiles.
__global__ void __launch_bounds__(256) conv_halfT_kernel(const float* __restrict__ W,
                                                         __half* __restrict__ hi,
                                                         int K, int N) {
    __shared__ float sh[32][33];
    const int n0 = blockIdx.x * 32, k0 = blockIdx.y * 32;
    const int tid = threadIdx.x;
    {
        int r = tid >> 3, c4 = (tid & 7) * 4;
        float4 v = *(const float4*)(W + (size_t)(k0 + r) * N + n0 + c4);
        sh[r][c4] = v.x; sh[r][c4 + 1] = v.y; sh[r][c4 + 2] = v.z; sh[r][c4 + 3] = v.w;
    }
    __syncthreads();
    {
        int nr = tid >> 3, kc4 = (tid & 7) * 4;
        __half h0 = __float2half_rn(sh[kc4][nr]);
        __half h1 = __float2half_rn(sh[kc4 + 1][nr]);
        __half h2 = __float2half_rn(sh[kc4 + 2][nr]);
        __half h3 = __float2half_rn(sh[kc4 + 3][nr]);
        size_t off = (size_t)(n0 + nr) * K + k0 + kc4;
        *(__half2*)(hi + off)     = __half2{h0, h1};
        *(__half2*)(hi + off + 2) = __half2{h2, h3};
    }
}

// ================= HMMA fp16 1-pass GEMM (v3: 256x128 CTA, 64x64 warp) =====
// 8 warps (4m x 2n), K-step 32, 4-stage cp.async ring.
// Stage = A(256x64B=16KB) | B(128x64B=8KB) = 24KB; x4 = 96KB; 1 CTA/SM.
#define HSTAGE 24576
#define HSMEM_TOTAL (4*HSTAGE)

__global__ void __launch_bounds__(256, 1) hgemm_kernel(const __half* __restrict__ Ah,
                                                       const __half* __restrict__ Bh,
                                                       const float* __restrict__ addsrc,
                                                       float* __restrict__ C,
                                                       int M, int N, int K) {
    extern __shared__ char smem[];
    const uint32_t sb = smem_u32(smem);
    const int tid = threadIdx.x;
    const int lane = tid & 31, wid = tid >> 5;
    const int bm = blockIdx.y * 256, bn = blockIdx.x * 128;
    const int Ks = K >> 5;

    const int wm = wid & 3, wn = wid >> 2;
    const int m0 = wm * 64, nb = wn * 64;

    float acc[4][8][4];
    #pragma unroll
    for (int a = 0; a < 4; a++)
        #pragma unroll
        for (int b = 0; b < 8; b++)
            #pragma unroll
            for (int c = 0; c < 4; c++) acc[a][b][c] = 0.0f;

    auto load_step = [&](int s, int stage) {
        const int k0 = s << 5;
        const uint32_t dbase = sb + stage * HSTAGE;
        #pragma unroll
        for (int i = 0; i < 4; i++) {          // A: 256 rows x 4 chunks
            int idx = tid + 256 * i;
            int row = idx >> 2, ch = idx & 3;
            cpasync16(dbase + SWZ64(row * 64 + ch * 16),
                      Ah + (size_t)(bm + row) * K + k0 + ch * 8);
        }
        #pragma unroll
        for (int i = 0; i < 2; i++) {          // B: 128 rows x 4 chunks
            int idx = tid + 256 * i;
            int row = idx >> 2, ch = idx & 3;
            cpasync16(dbase + 16384 + SWZ64(row * 64 + ch * 16),
                      Bh + (size_t)(bn + row) * K + k0 + ch * 8);
        }
        asm volatile("cp.async.commit_group;" ::: "memory");
    };

    load_step(0, 0);
    load_step(1, 1);
    load_step(2, 2);

    const int arow = lane & 15;
    const int akb  = (lane >> 4) << 4;
    const int brow = ((lane >> 4) << 3) + (lane & 7);
    const int bkb  = ((lane >> 3) & 1) << 4;

    for (int s = 0; s < Ks; s++) {
        const int stage = s & 3;
        const int rem = Ks - 1 - s;
        if (rem >= 2)      asm volatile("cp.async.wait_group 2;" ::: "memory");
        else if (rem == 1) asm volatile("cp.async.wait_group 1;" ::: "memory");
        else               asm volatile("cp.async.wait_group 0;" ::: "memory");
        __syncthreads();
        if (s + 3 < Ks) load_step(s + 3, (s + 3) & 3);
        const uint32_t base = sb + stage * HSTAGE;
        #pragma unroll
        for (int kk = 0; kk < 2; kk++) {
            uint32_t ah[4][4], bb[4][4];
            #pragma unroll
            for (int mi = 0; mi < 4; mi++)
                ldsm4(ah[mi], base + SWZ64((m0 + mi * 16 + arow) * 64 + kk * 32 + akb));
            #pragma unroll
            for (int nj = 0; nj < 4; nj++)
                ldsm4(bb[nj], base + 16384 + SWZ64((nb + nj * 16 + brow) * 64 + kk * 32 + bkb));
            #pragma unroll
            for (int mi = 0; mi < 4; mi++)
                #pragma unroll
                for (int nt = 0; nt < 8; nt++)
                    mma16816(acc[mi][nt], ah[mi], &bb[nt >> 1][(nt & 1) * 2]);
        }
    }

    #pragma unroll
    for (int mi = 0; mi < 4; mi++) {
        #pragma unroll
        for (int nt = 0; nt < 8; nt++) {
            int row = bm + m0 + mi * 16 + (lane >> 2);
            int col = bn + nb + nt * 8 + (lane & 3) * 2;
            size_t off0 = (size_t)row * N + col;
            size_t off1 = off0 + (size_t)8 * N;
            float2 v0 = { acc[mi][nt][0], acc[mi][nt][1] };
            float2 v1 = { acc[mi][nt][2], acc[mi][nt][3] };
            if (addsrc) {
                float2 a0 = *(const float2*)(addsrc + off0);
                float2 a1 = *(const float2*)(addsrc + off1);
                v0.x += a0.x; v0.y += a0.y; v1.x += a1.x; v1.y += a1.y;
            }
            *(float2*)(C + off0) = v0;
            *(float2*)(C + off1) = v1;
        }
    }
}

// ---------------- causal conv(K=4)+SiLU, strided input ----------------
__device__ __forceinline__ float conv_at(const float* __restrict__ x, size_t idx,
                                         int t, const float* __restrict__ w, int d,
                                         int stride) {
    float acc = x[idx] * w[d * 4 + 3];
    if (t >= 1) acc += x[idx - stride]     * w[d * 4 + 2];
    if (t >= 2) acc += x[idx - 2 * stride] * w[d * 4 + 1];
    if (t >= 3) acc += x[idx - 3 * stride] * w[d * 4 + 0];
    return acc;
}

__global__ void __launch_bounds__(256) conv_silu_kernel(const float* __restrict__ x,
                                                        const float* __restrict__ w,
                                                        float* __restrict__ out) {
    unsigned int idx = blockIdx.x * 256 + threadIdx.x;
    int d = (int)(idx & (DD - 1));
    int row = (int)(idx >> 11);
    int t = row & (TT - 1);
    size_t src = (size_t)row * NQKVG + d;
    float acc = conv_at(x, src, t, w, d, NQKVG);
    out[idx] = acc * sigf(acc);
}

// fused conv+SiLU+RoPE with per-token decay prefold
__global__ void __launch_bounds__(256) conv_silu_rope_kernel(const float* __restrict__ x,
                                                             const float* __restrict__ w,
                                                             float* __restrict__ out,
                                                             float base, float sign) {
    int idx = blockIdx.x * 256 + threadIdx.x;
    int j = idx & 127;
    int h = (idx >> 7) & 7;
    int bt = idx >> 10;
    int t = bt & (TT - 1);
    int d1 = h * DK + j;
    int d2 = d1 + 128;
    size_t i1 = (size_t)bt * NQKVG + d1;
    size_t i2 = i1 + 128;
    float a1 = conv_at(x, i1, t, w, d1, NQKVG);
    float a2 = conv_at(x, i2, t, w, d2, NQKVG);
    a1 *= sigf(a1);
    a2 *= sigf(a2);
    float inv = powf(10000.0f, -(float)(2 * j) * (1.0f / 256.0f));
    float fr = (float)t * inv;
    float s, c;
    sincosf(fr, &s, &c);
    float gam = 1.0f - exp2f(-5.0f - (float)h);
    float scale = base * powf(gam, sign * (float)((t & 63) + 1));
    size_t o1 = (size_t)bt * DD + d1;
    out[o1]       = (a1 * c - a2 * s) * scale;
    out[o1 + 128] = (a2 * c + a1 * s) * scale;
}

// ---------------- retention pass A: per-chunk KV summary (fp16 M) ----------
__global__ void __launch_bounds__(256) chunk_kv_kernel(const float* __restrict__ k,
                                                       const float* __restrict__ v,
                                                       __half* __restrict__ M) {
    __shared__ float kt[64][68];
    __shared__ float vt[64][68];
    const int tile = blockIdx.x;
    const int d0 = (tile >> 2) * 64, e0 = (tile & 3) * 64;
    const int chunk = blockIdx.y, bh = blockIdx.z;
    const int b = bh >> 3, h = bh & 7;
    const float gam = 1.0f - exp2f(-5.0f - (float)h);
    const float gC64 = powf(gam, 64.0f);
    const int tid = threadIdx.x;
    const size_t rowbase = ((size_t)b * TT + chunk * CK) * DD + h * DK;

    for (int l = tid; l < 64 * 64; l += 256) {
        int r = l >> 6, c = l & 63;
        kt[r][c] = k[rowbase + (size_t)r * DD + d0 + c] * gC64;
        vt[r][c] = v[rowbase + (size_t)r * DD + e0 + c];
    }
    __syncthreads();

    const int dt = tid >> 4, et = tid & 15;
    unsigned long long acc[4][2];
    #pragma unroll
    for (int r = 0; r < 4; r++) { acc[r][0] = 0ull; acc[r][1] = 0ull; }
    for (int j = 0; j < 64; j++) {
        float4 kd = *(const float4*)&kt[j][dt * 4];
        float4 ve = *(const float4*)&vt[j][et * 4];
        unsigned long long vp0 = pk2(ve.x, ve.y), vp1 = pk2(ve.z, ve.w);
        float kr[4] = { kd.x, kd.y, kd.z, kd.w };
        #pragma unroll
        for (int r = 0; r < 4; r++) {
            unsigned long long kp = pk2(kr[r], kr[r]);
            fma2(acc[r][0], kp, vp0);
            fma2(acc[r][1], kp, vp1);
        }
    }
    size_t mbase = (((size_t)bh * NC + chunk) << 16);
    #pragma unroll
    for (int r = 0; r < 4; r++) {
        float2 v0 = up2(acc[r][0]), v1 = up2(acc[r][1]);
        size_t p = mbase + (size_t)(d0 + dt * 4 + r) * DV + e0 + et * 4;
        *(__half2*)(M + p)     = __floats2half2_rn(v0.x, v0.y);
        *(__half2*)(M + p + 2) = __floats2half2_rn(v1.x, v1.y);
    }
}

// ---------------- retention pass B: state scan (fp16 in/out, fp32 accum) ---
__global__ void __launch_bounds__(256) scan_state_kernel(const __half* __restrict__ M,
                                                         __half* __restrict__ S) {
    int idx4 = (blockIdx.x * 256 + threadIdx.x) * 4;
    int bh = idx4 >> 16;
    float gam = 1.0f - exp2f(-5.0f - (float)(bh & 7));
    float gC = powf(gam, 64.0f);
    size_t base = ((size_t)bh * NC << 16) + (idx4 & 65535);
    float4 s = {0.0f, 0.0f, 0.0f, 0.0f};
    for (int c = 0; c < NC; c++) {
        size_t p = base + ((size_t)c << 16);
        *(__half2*)(S + p)     = __floats2half2_rn(s.x, s.y);
        *(__half2*)(S + p + 2) = __floats2half2_rn(s.z, s.w);
        __half2 m01 = *(const __half2*)(M + p);
        __half2 m23 = *(const __half2*)(M + p + 2);
        float2 f01 = __half22float2(m01);
        float2 f23 = __half22float2(m23);
        s.x = gC * s.x + f01.x; s.y = gC * s.y + f01.y;
        s.z = gC * s.z + f23.x; s.w = gC * s.w + f23.y;
    }
}

// ---------------- retention pass C: per-chunk output (2-row tiling) --------
__global__ void __launch_bounds__(256) retention_out_kernel(const float* __restrict__ q,
                                                            const float* __restrict__ k,
                                                            const float* __restrict__ v,
                                                            const __half* __restrict__ S,
                                                            float* __restrict__ o) {
    __shared__ float Asm[64][65];
    __shared__ float t0[64][33];
    __shared__ float t1t[32][66];
    __shared__ float st[8][256];
    __shared__ float qs[8][64];
    const int chunk = blockIdx.x, bh = blockIdx.y;
    const int b = bh >> 3;
    const int tid = threadIdx.x;
    const size_t rowbase = ((size_t)b * TT + chunk * CK) * DD + (bh & 7) * DK;
    const int i2 = tid >> 3;
    const int eo = tid & 7;

    // ---- step 1: A = q2 k2^T ----
    {
        const int jg = eo * 8;
        unsigned long long accA[2][4];
        #pragma unroll
        for (int r = 0; r < 2; r++)
            #pragma unroll
            for (int p = 0; p < 4; p++) accA[r][p] = 0ull;
        for (int d0 = 0; d0 < 256; d0 += 32) {
            for (int l = tid; l < 2048; l += 256) {
                int r = l >> 5, c = l & 31;
                t0[r][c] = q[rowbase + (size_t)r * DD + d0 + c];
            }
            for (int l = tid; l < 2048; l += 256) {
                int dd = l & 31, jj = l >> 5;
                t1t[dd][jj] = k[rowbase + (size_t)jj * DD + d0 + dd];
            }
            __syncthreads();
            for (int dd = 0; dd < 32; dd++) {
                float q0 = t0[i2][dd], q1 = t0[i2 + 32][dd];
                unsigned long long qp0 = pk2(q0, q0), qp1 = pk2(q1, q1);
                const unsigned long long* kp = (const unsigned long long*)&t1t[dd][jg];
                #pragma unroll
                for (int p = 0; p < 4; p++) {
                    unsigned long long kv = kp[p];
                    fma2(accA[0][p], qp0, kv);
                    fma2(accA[1][p], qp1, kv);
                }
            }
            __syncthreads();
        }
        #pragma unroll
        for (int r = 0; r < 2; r++) {
            int i = i2 + 32 * r;
            #pragma unroll
            for (int p = 0; p < 4; p++) {
                float2 a = up2(accA[r][p]);
                int j0 = jg + 2 * p;
                Asm[i][j0]     = (i >= j0)     ? a.x : 0.0f;
                Asm[i][j0 + 1] = (i >= j0 + 1) ? a.y : 0.0f;
            }
        }
    }
    __syncthreads();

    // ---- step 2: o[i][e] ----
    unsigned long long acc[2][16];
    #pragma unroll
    for (int r = 0; r < 2; r++)
        #pragma unroll
        for (int m = 0; m < 16; m++) acc[r][m] = 0ull;

    // 2a: A @ v
    for (int j0 = 0; j0 < 64; j0 += 8) {
        for (int l = tid; l < 2048; l += 256) {
            int r = l >> 8, c = l & 255;
            st[r][c] = v[rowbase + (size_t)(j0 + r) * DD + c];
        }
        __syncthreads();
        #pragma unroll
        for (int jj = 0; jj < 8; jj++) {
            float a0 = Asm[i2][j0 + jj], a1 = Asm[i2 + 32][j0 + jj];
            unsigned long long ap0 = pk2(a0, a0), ap1 = pk2(a1, a1);
            const unsigned long long* vp = (const unsigned long long*)st[jj];
            #pragma unroll
            for (int m = 0; m < 16; m++) {
                unsigned long long sv = vp[eo + 8 * m];
                fma2(acc[0][m], ap0, sv);
                fma2(acc[1][m], ap1, sv);
            }
        }
        __syncthreads();
    }

    // 2b: + q2 @ S (S in fp16, converted on smem load)
    {
        const __half* Sb = S + (((size_t)bh * NC + chunk) << 16);
        for (int d0 = 0; d0 < 256; d0 += 8) {
            for (int l = tid; l < 1024; l += 256) {
                int r = l >> 7, c2 = (l & 127) * 2;
                __half2 hv = *(const __half2*)(Sb + (size_t)(d0 + r) * DV + c2);
                float2 fv = __half22float2(hv);
                st[r][c2] = fv.x; st[r][c2 + 1] = fv.y;
            }
            for (int l = tid; l < 512; l += 256) {
                int dd = l & 7, i = l >> 3;
                qs[dd][i] = q[rowbase + (size_t)i * DD + d0 + dd];
            }
            __syncthreads();
            #pragma unroll
            for (int dd = 0; dd < 8; dd++) {
                float q0 = qs[dd][i2], q1 = qs[dd][i2 + 32];
                unsigned long long qp0 = pk2(q0, q0), qp1 = pk2(q1, q1);
                const unsigned long long* sp = (const unsigned long long*)st[dd];
                #pragma unroll
                for (int m = 0; m < 16; m++) {
                    unsigned long long sv = sp[eo + 8 * m];
                    fma2(acc[0][m], qp0, sv);
                    fma2(acc[1][m], qp1, sv);
                }
            }
            __syncthreads();
        }
    }

    #pragma unroll
    for (int r = 0; r < 2; r++) {
        float* ob = o + rowbase + (size_t)(i2 + 32 * r) * DD;
        #pragma unroll
        for (int m = 0; m < 16; m++) {
            float2 rr = up2(acc[r][m]);
            int e = 2 * (eo + 8 * m);
            ob[e] = rr.x; ob[e + 1] = rr.y;
        }
    }
}

// ---------------- per-head rmsnorm(o)*silu(g) -> fp16 (g strided) ----------
__global__ void __launch_bounds__(256) gnorm_half_kernel(const float* __restrict__ o,
                                                         const float* __restrict__ g,
                                                         const float* __restrict__ w,
                                                         __half* __restrict__ hi) {
    const int row = blockIdx.x >> 3, hh = blockIdx.x & 7;
    const size_t base = (size_t)row * DD + hh * DV;
    const size_t gbase = (size_t)row * NQKVG + hh * DV;
    const int tid = threadIdx.x;
    float val = o[base + tid];
    float tot = block_sum_256(val * val);
    float rinv = rsqrtf(tot * (1.0f / (float)DV) + EPSV);
    float gv = g[gbase + tid];
    hi[base + tid] = __float2half_rn(val * rinv * w[tid] * gv * sigf(gv));
}

// ---------------- SwiGLU -> fp16 ----------------
__global__ void __launch_bounds__(256) swiglu_half_kernel(const float* __restrict__ gy,
                                                          __half* __restrict__ hi) {
    unsigned int idx2 = blockIdx.x * 256 + threadIdx.x;
    unsigned int row = idx2 / (INTER / 2);
    unsigned int c = (idx2 - row * (INTER / 2)) * 2;
    size_t p = (size_t)row * (2 * INTER) + c;
    float g0 = gy[p],         g1 = gy[p + 1];
    float y0 = gy[p + INTER], y1 = gy[p + INTER + 1];
    float u0 = g0 * sigf(g0) * y0;
    float u1 = g1 * sigf(g1) * y1;
    size_t q = (size_t)row * INTER + c;
    *(__half2*)(hi + q) = __half2{__float2half_rn(u0), __float2half_rn(u1)};
}

// ---------------- launch ----------------
extern "C" void kernel_launch(void* const* d_in, const int* in_sizes, int n_in,
                              void* d_out, int out_size) {
    (void)in_sizes; (void)n_in; (void)out_size;
    const float* hidden      = (const float*)d_in[0];
    const float* attn_norm_w = (const float*)d_in[1];
    const float* Wq          = (const float*)d_in[2];
    const float* Wk          = (const float*)d_in[3];
    const float* Wv          = (const float*)d_in[4];
    const float* Wg          = (const float*)d_in[5];
    const float* Wo          = (const float*)d_in[6];
    const float* conv_wq     = (const float*)d_in[7];
    const float* conv_wk     = (const float*)d_in[8];
    const float* conv_wv     = (const float*)d_in[9];
    const float* gnorm_w     = (const float*)d_in[10];
    const float* mlp_norm_w  = (const float*)d_in[11];
    const float* W_gate      = (const float*)d_in[12];
    const float* W_down      = (const float*)d_in[13];
    float* out = (float*)d_out;

    float *pqkvg, *pq, *pk, *pv, *po, *ph, *pgy;
    __half *pM, *pS, *pah, *pbh;
    cudaGetSymbolAddress((void**)&pqkvg, g_qkvg);
    cudaGetSymbolAddress((void**)&pq,  g_q);
    cudaGetSymbolAddress((void**)&pk,  g_k);
    cudaGetSymbolAddress((void**)&pv,  g_v);
    cudaGetSymbolAddress((void**)&pM,  g_M);
    cudaGetSymbolAddress((void**)&pS,  g_S);
    cudaGetSymbolAddress((void**)&po,  g_o);
    cudaGetSymbolAddress((void**)&ph,  g_h);
    cudaGetSymbolAddress((void**)&pgy, g_gy);
    cudaGetSymbolAddress((void**)&pah, g_ah);
    cudaGetSymbolAddress((void**)&pbh, g_bh);

    cudaFuncSetAttribute(hgemm_kernel, cudaFuncAttributeMaxDynamicSharedMemorySize, HSMEM_TOTAL);

    const dim3 gQKVG(NQKVG / 128, NTOK / 256);        // 64 x 16
    const dim3 gD(DD / 128, NTOK / 256);              // 16 x 16
    const dim3 gGate((2 * INTER) / 128, NTOK / 256);  // 44 x 16
    const dim3 tD(DD / 32, DD / 32);
    const dim3 tGate((2 * INTER) / 32, DD / 32);
    const dim3 tDown(DD / 32, INTER / 32);

    // x = rmsnorm(hidden) -> fp16
    rmsnorm_half_kernel<<<NTOK, 256>>>(hidden, attn_norm_w, pah);

    // batched q|k|v|g projection (one N=8192 GEMM)
    conv_halfT_kernel<<<tD, 256>>>(Wq, pbh,                          DD, DD);
    conv_halfT_kernel<<<tD, 256>>>(Wk, pbh + (size_t)1 * DD * DD,    DD, DD);
    conv_halfT_kernel<<<tD, 256>>>(Wv, pbh + (size_t)2 * DD * DD,    DD, DD);
    conv_halfT_kernel<<<tD, 256>>>(Wg, pbh + (size_t)3 * DD * DD,    DD, DD);
    hgemm_kernel<<<gQKVG, 256, HSMEM_TOTAL>>>(pah, pbh, nullptr, pqkvg, NTOK, NQKVG, DD);

    // conv+silu (+rope + decay prefold for q,k)
    conv_silu_rope_kernel<<<(NTOK * HH * 128) / 256, 256>>>(pqkvg,      conv_wq, pq, 0.0625f,  1.0f);
    conv_silu_rope_kernel<<<(NTOK * HH * 128) / 256, 256>>>(pqkvg + DD, conv_wk, pk, 1.0f,    -1.0f);
    conv_silu_kernel<<<(NTOK * DD) / 256, 256>>>(pqkvg + 2 * DD, conv_wv, pv);

    chunk_kv_kernel<<<dim3(16, NC, BB * HH), 256>>>(pk, pv, pM);
    scan_state_kernel<<<(BB * HH * DK * DV / 4) / 256, 256>>>(pM, pS);
    retention_out_kernel<<<dim3(NC, BB * HH), 256>>>(pq, pk, pv, pS, po);

    // gated norm -> fp16 (g read from qkvg panel 3)
    gnorm_half_kernel<<<NTOK * HH, 256>>>(po, pqkvg + 3 * DD, gnorm_w, pah);

    // h = o2 @ Wo + hidden
    conv_halfT_kernel<<<tD, 256>>>(Wo, pbh, DD, DD);
    hgemm_kernel<<<gD, 256, HSMEM_TOTAL>>>(pah, pbh, hidden, ph, NTOK, DD, DD);

    // MLP
    rmsnorm_half_kernel<<<NTOK, 256>>>(ph, mlp_norm_w, pah);
    conv_halfT_kernel<<<tGate, 256>>>(W_gate, pbh, DD, 2 * INTER);
    hgemm_kernel<<<gGate, 256, HSMEM_TOTAL>>>(pah, pbh, nullptr, pgy, NTOK, 2 * INTER, DD);

    swiglu_half_kernel<<<(NTOK * INTER / 2) / 256, 256>>>(pgy, pah);
    conv_halfT_kernel<<<tDown, 256>>>(W_down, pbh, INTER, DD);
    hgemm_kernel<<<gD, 256, HSMEM_TOTAL>>>(pah, pbh, ph, out, NTOK, DD, INTER);
}

// round 15
// speedup vs baseline: 1.0663x; 1.0663x over previous
#include <cuda_runtime.h>
#include <cuda_bf16.h>
#include <cuda_fp16.h>
#include <math.h>
#include <stdint.h>

// ---------------- problem constants ----------------
#define BB 2
#define TT 2048
#define DD 2048
#define HH 8
#define DK 256
#define DV 256
#define NC 32          // T / CHUNK
#define CK 64          // chunk size
#define INTER 2816
#define EPSV 1e-5f
#define NQKVG 8192     // batched projection width

// ---------------- scratch (device globals; no allocations allowed) ----------
#define NTOK (BB*TT)               // 4096
__device__ float g_qkvg[NTOK*NQKVG];   // batched q|k|v|g projections
__device__ float g_q  [NTOK*DD];       // q2 (prescaled)
__device__ float g_k  [NTOK*DD];       // k2 (prescaled)
__device__ float g_v  [NTOK*DD];
__device__ __half g_M [BB*HH*NC*DK*DV];   // fp16 chunk KV summaries
__device__ __half g_S [BB*HH*NC*DK*DV];   // fp16 per-chunk states
__device__ float g_o  [NTOK*DD];
__device__ float g_h  [NTOK*DD];
__device__ float g_gy [NTOK*2*INTER];

// fp16 buffers (A: activations, B: transposed weights)
#define AMAX (NTOK*INTER)
#define BMAX (4*DD*DD)
__device__ __align__(256) __half g_ah[AMAX];
__device__ __align__(256) __half g_bh[BMAX];

// ---------------- f32x2 packed-FMA helpers ----------------
__device__ __forceinline__ unsigned long long pk2(float lo, float hi) {
    unsigned long long r;
    asm("mov.b64 %0, {%1, %2};" : "=l"(r) : "f"(lo), "f"(hi));
    return r;
}
__device__ __forceinline__ void fma2(unsigned long long& c, unsigned long long a, unsigned long long b) {
    asm("fma.rn.f32x2 %0, %1, %2, %0;" : "+l"(c) : "l"(a), "l"(b));
}
__device__ __forceinline__ float2 up2(unsigned long long v) {
    float2 r;
    asm("mov.b64 {%0, %1}, %2;" : "=f"(r.x), "=f"(r.y) : "l"(v));
    return r;
}

__device__ __forceinline__ float sigf(float x) { return 1.0f / (1.0f + expf(-x)); }

__device__ __forceinline__ float block_sum_256(float v) {
    __shared__ float red[8];
    __shared__ float tot;
    #pragma unroll
    for (int o = 16; o; o >>= 1) v += __shfl_xor_sync(0xffffffffu, v, o);
    int tid = threadIdx.x;
    if ((tid & 31) == 0) red[tid >> 5] = v;
    __syncthreads();
    if (tid == 0) {
        float t = red[0];
        #pragma unroll
        for (int i = 1; i < 8; i++) t += red[i];
        tot = t;
    }
    __syncthreads();
    return tot;
}

// ================= baseline-PTX MMA helpers =================
__device__ __forceinline__ uint32_t smem_u32(const void* p) {
    uint32_t a;
    asm("{ .reg .u64 t; cvta.to.shared.u64 t, %1; cvt.u32.u64 %0, t; }" : "=r"(a) : "l"(p));
    return a;
}
#define SWZ64(off) ((off) ^ ((((unsigned)(off)) >> 3) & 0x30u))

__device__ __forceinline__ void ldsm4(uint32_t* r, uint32_t addr) {
    asm volatile("ldmatrix.sync.aligned.m8n8.x4.shared.b16 {%0,%1,%2,%3}, [%4];"
                 : "=r"(r[0]), "=r"(r[1]), "=r"(r[2]), "=r"(r[3]) : "r"(addr));
}
__device__ __forceinline__ void mma16816(float* d, const uint32_t* a, const uint32_t* b) {
    asm volatile(
        "mma.sync.aligned.m16n8k16.row.col.f32.f16.f16.f32 "
        "{%0,%1,%2,%3}, {%4,%5,%6,%7}, {%8,%9}, {%0,%1,%2,%3};"
        : "+f"(d[0]), "+f"(d[1]), "+f"(d[2]), "+f"(d[3])
        : "r"(a[0]), "r"(a[1]), "r"(a[2]), "r"(a[3]), "r"(b[0]), "r"(b[1]));
}
__device__ __forceinline__ void cpasync16(uint32_t dst, const void* src) {
    asm volatile("cp.async.cg.shared.global [%0], [%1], 16;" :: "r"(dst), "l"(src));
}

// ================= conversion / fused elementwise kernels =================

__global__ void __launch_bounds__(256) rmsnorm_half_kernel(const float* __restrict__ in,
                                                           const float* __restrict__ w,
                                                           __half* __restrict__ hi) {
    const size_t base = (size_t)blockIdx.x * DD;
    const int tid = threadIdx.x;
    float4 v0 = *(const float4*)(in + base + tid * 4);
    float4 v1 = *(const float4*)(in + base + 1024 + tid * 4);
    float ss = v0.x*v0.x + v0.y*v0.y + v0.z*v0.z + v0.w*v0.w
             + v1.x*v1.x + v1.y*v1.y + v1.z*v1.z + v1.w*v1.w;
    float tot = block_sum_256(ss);
    float rinv = rsqrtf(tot * (1.0f / (float)DD) + EPSV);
    float4 w0 = *(const float4*)(w + tid * 4);
    float4 w1 = *(const float4*)(w + 1024 + tid * 4);
    size_t o0 = base + tid * 4, o1 = base + 1024 + tid * 4;
    *(__half2*)(hi + o0)     = __half2{__float2half_rn(v0.x*rinv*w0.x), __float2half_rn(v0.y*rinv*w0.y)};
    *(__half2*)(hi + o0 + 2) = __half2{__float2half_rn(v0.z*rinv*w0.z), __float2half_rn(v0.w*rinv*w0.w)};
    *(__half2*)(hi + o1)     = __half2{__float2half_rn(v1.x*rinv*w1.x), __float2half_rn(v1.y*rinv*w1.y)};
    *(__half2*)(hi + o1 + 2) = __half2{__float2half_rn(v1.z*rinv*w1.z), __float2half_rn(v1.w*rinv*w1.w)};
}

// W[K][N] fp32 -> Bt[N][K] fp16 (transpose). 32x32 tiles.
__global__ void __launch_bounds__(256) conv_halfT_kernel(const float* __restrict__ W,
                                                         __half* __restrict__ hi,
                                                         int K, int N) {
    __shared__ float sh[32][33];
    const int n0 = blockIdx.x * 32, k0 = blockIdx.y * 32;
    const int tid = threadIdx.x;
    {
        int r = tid >> 3, c4 = (tid & 7) * 4;
        float4 v = *(const float4*)(W + (size_t)(k0 + r) * N + n0 + c4);
        sh[r][c4] = v.x; sh[r][c4 + 1] = v.y; sh[r][c4 + 2] = v.z; sh[r][c4 + 3] = v.w;
    }
    __syncthreads();
    {
        int nr = tid >> 3, kc4 = (tid & 7) * 4;
        __half h0 = __float2half_rn(sh[kc4][nr]);
        __half h1 = __float2half_rn(sh[kc4 + 1][nr]);
        __half h2 = __float2half_rn(sh[kc4 + 2][nr]);
        __half h3 = __float2half_rn(sh[kc4 + 3][nr]);
        size_t off = (size_t)(n0 + nr) * K + k0 + kc4;
        *(__half2*)(hi + off)     = __half2{h0, h1};
        *(__half2*)(hi + off + 2) = __half2{h2, h3};
    }
}

// ================= HMMA fp16 1-pass GEMM (R13 config: 128x128, 2 CTA/SM) ===
#define HSTAGE 16384
#define HSMEM_TOTAL (4*HSTAGE)

__global__ void __launch_bounds__(256, 2) hgemm_kernel(const __half* __restrict__ Ah,
                                                       const __half* __restrict__ Bh,
                                                       const float* __restrict__ addsrc,
                                                       float* __restrict__ C,
                                                       int M, int N, int K) {
    extern __shared__ char smem[];
    const uint32_t sb = smem_u32(smem);
    const int tid = threadIdx.x;
    const int lane = tid & 31, wid = tid >> 5;
    const int bm = blockIdx.y * 128, bn = blockIdx.x * 128;
    const int Ks = K >> 5;

    const int wm = wid & 3, wn = wid >> 2;
    const int m0 = wm * 32, nb = wn * 64;

    float acc[2][8][4];
    #pragma unroll
    for (int a = 0; a < 2; a++)
        #pragma unroll
        for (int b = 0; b < 8; b++)
            #pragma unroll
            for (int c = 0; c < 4; c++) acc[a][b][c] = 0.0f;

    const int lrow = tid >> 2, lch = tid & 3;

    auto load_step = [&](int s, int stage) {
        const int k0 = s << 5;
        const uint32_t so0 = SWZ64(lrow * 64 + lch * 16);
        const uint32_t so1 = SWZ64((lrow + 64) * 64 + lch * 16);
        {
            const __half* src = Ah + (size_t)bm * K + k0 + lch * 8;
            const uint32_t dbase = sb + stage * HSTAGE;
            cpasync16(dbase + so0, src + (size_t)lrow * K);
            cpasync16(dbase + so1, src + (size_t)(lrow + 64) * K);
        }
        {
            const __half* src = Bh + (size_t)bn * K + k0 + lch * 8;
            const uint32_t dbase = sb + stage * HSTAGE + 8192;
            cpasync16(dbase + so0, src + (size_t)lrow * K);
            cpasync16(dbase + so1, src + (size_t)(lrow + 64) * K);
        }
        asm volatile("cp.async.commit_group;" ::: "memory");
    };

    load_step(0, 0);
    load_step(1, 1);
    load_step(2, 2);

    const int arow = lane & 15;
    const int akb  = (lane >> 4) << 4;
    const int brow = ((lane >> 4) << 3) + (lane & 7);
    const int bkb  = ((lane >> 3) & 1) << 4;

    for (int s = 0; s < Ks; s++) {
        const int stage = s & 3;
        const int rem = Ks - 1 - s;
        if (rem >= 2)      asm volatile("cp.async.wait_group 2;" ::: "memory");
        else if (rem == 1) asm volatile("cp.async.wait_group 1;" ::: "memory");
        else               asm volatile("cp.async.wait_group 0;" ::: "memory");
        __syncthreads();
        if (s + 3 < Ks) load_step(s + 3, (s + 3) & 3);
        const uint32_t base = sb + stage * HSTAGE;
        #pragma unroll
        for (int kk = 0; kk < 2; kk++) {
            uint32_t ah[2][4], bb[4][4];
            #pragma unroll
            for (int mi = 0; mi < 2; mi++) {
                uint32_t aoff = SWZ64((m0 + mi * 16 + arow) * 64 + kk * 32 + akb);
                ldsm4(ah[mi], base + aoff);
            }
            #pragma unroll
            for (int nj = 0; nj < 4; nj++)
                ldsm4(bb[nj], base + 8192 + SWZ64((nb + nj * 16 + brow) * 64 + kk * 32 + bkb));
            #pragma unroll
            for (int mi = 0; mi < 2; mi++)
                #pragma unroll
                for (int nt = 0; nt < 8; nt++)
                    mma16816(acc[mi][nt], ah[mi], &bb[nt >> 1][(nt & 1) * 2]);
        }
    }

    #pragma unroll
    for (int mi = 0; mi < 2; mi++) {
        #pragma unroll
        for (int nt = 0; nt < 8; nt++) {
            int row = bm + m0 + mi * 16 + (lane >> 2);
            int col = bn + nb + nt * 8 + (lane & 3) * 2;
            size_t off0 = (size_t)row * N + col;
            size_t off1 = off0 + (size_t)8 * N;
            float2 v0 = { acc[mi][nt][0], acc[mi][nt][1] };
            float2 v1 = { acc[mi][nt][2], acc[mi][nt][3] };
            if (addsrc) {
                float2 a0 = *(const float2*)(addsrc + off0);
                float2 a1 = *(const float2*)(addsrc + off1);
                v0.x += a0.x; v0.y += a0.y; v1.x += a1.x; v1.y += a1.y;
            }
            *(float2*)(C + off0) = v0;
            *(float2*)(C + off1) = v1;
        }
    }
}

// ---------------- causal conv(K=4)+SiLU, strided input ----------------
__device__ __forceinline__ float conv_at(const float* __restrict__ x, size_t idx,
                                         int t, const float* __restrict__ w, int d,
                                         int stride) {
    float acc = x[idx] * w[d * 4 + 3];
    if (t >= 1) acc += x[idx - stride]     * w[d * 4 + 2];
    if (t >= 2) acc += x[idx - 2 * stride] * w[d * 4 + 1];
    if (t >= 3) acc += x[idx - 3 * stride] * w[d * 4 + 0];
    return acc;
}

__global__ void __launch_bounds__(256) conv_silu_kernel(const float* __restrict__ x,
                                                        const float* __restrict__ w,
                                                        float* __restrict__ out) {
    unsigned int idx = blockIdx.x * 256 + threadIdx.x;
    int d = (int)(idx & (DD - 1));
    int row = (int)(idx >> 11);
    int t = row & (TT - 1);
    size_t src = (size_t)row * NQKVG + d;
    float acc = conv_at(x, src, t, w, d, NQKVG);
    out[idx] = acc * sigf(acc);
}

// fused conv+SiLU+RoPE with per-token decay prefold
__global__ void __launch_bounds__(256) conv_silu_rope_kernel(const float* __restrict__ x,
                                                             const float* __restrict__ w,
                                                             float* __restrict__ out,
                                                             float base, float sign) {
    int idx = blockIdx.x * 256 + threadIdx.x;
    int j = idx & 127;
    int h = (idx >> 7) & 7;
    int bt = idx >> 10;
    int t = bt & (TT - 1);
    int d1 = h * DK + j;
    int d2 = d1 + 128;
    size_t i1 = (size_t)bt * NQKVG + d1;
    size_t i2 = i1 + 128;
    float a1 = conv_at(x, i1, t, w, d1, NQKVG);
    float a2 = conv_at(x, i2, t, w, d2, NQKVG);
    a1 *= sigf(a1);
    a2 *= sigf(a2);
    float inv = powf(10000.0f, -(float)(2 * j) * (1.0f / 256.0f));
    float fr = (float)t * inv;
    float s, c;
    sincosf(fr, &s, &c);
    float gam = 1.0f - exp2f(-5.0f - (float)h);
    float scale = base * powf(gam, sign * (float)((t & 63) + 1));
    size_t o1 = (size_t)bt * DD + d1;
    out[o1]       = (a1 * c - a2 * s) * scale;
    out[o1 + 128] = (a2 * c + a1 * s) * scale;
}

// ---------------- retention pass A: per-chunk KV summary (fp16 M) ----------
__global__ void __launch_bounds__(256) chunk_kv_kernel(const float* __restrict__ k,
                                                       const float* __restrict__ v,
                                                       __half* __restrict__ M) {
    __shared__ float kt[64][68];
    __shared__ float vt[64][68];
    const int tile = blockIdx.x;
    const int d0 = (tile >> 2) * 64, e0 = (tile & 3) * 64;
    const int chunk = blockIdx.y, bh = blockIdx.z;
    const int b = bh >> 3, h = bh & 7;
    const float gam = 1.0f - exp2f(-5.0f - (float)h);
    const float gC64 = powf(gam, 64.0f);
    const int tid = threadIdx.x;
    const size_t rowbase = ((size_t)b * TT + chunk * CK) * DD + h * DK;

    for (int l = tid; l < 64 * 64; l += 256) {
        int r = l >> 6, c = l & 63;
        kt[r][c] = k[rowbase + (size_t)r * DD + d0 + c] * gC64;
        vt[r][c] = v[rowbase + (size_t)r * DD + e0 + c];
    }
    __syncthreads();

    const int dt = tid >> 4, et = tid & 15;
    unsigned long long acc[4][2];
    #pragma unroll
    for (int r = 0; r < 4; r++) { acc[r][0] = 0ull; acc[r][1] = 0ull; }
    for (int j = 0; j < 64; j++) {
        float4 kd = *(const float4*)&kt[j][dt * 4];
        float4 ve = *(const float4*)&vt[j][et * 4];
        unsigned long long vp0 = pk2(ve.x, ve.y), vp1 = pk2(ve.z, ve.w);
        float kr[4] = { kd.x, kd.y, kd.z, kd.w };
        #pragma unroll
        for (int r = 0; r < 4; r++) {
            unsigned long long kp = pk2(kr[r], kr[r]);
            fma2(acc[r][0], kp, vp0);
            fma2(acc[r][1], kp, vp1);
        }
    }
    size_t mbase = (((size_t)bh * NC + chunk) << 16);
    #pragma unroll
    for (int r = 0; r < 4; r++) {
        float2 v0 = up2(acc[r][0]), v1 = up2(acc[r][1]);
        size_t p = mbase + (size_t)(d0 + dt * 4 + r) * DV + e0 + et * 4;
        *(__half2*)(M + p)     = __floats2half2_rn(v0.x, v0.y);
        *(__half2*)(M + p + 2) = __floats2half2_rn(v1.x, v1.y);
    }
}

// ---------------- retention pass B: state scan (fp16 in/out, fp32 accum) ---
__global__ void __launch_bounds__(256) scan_state_kernel(const __half* __restrict__ M,
                                                         __half* __restrict__ S) {
    int idx4 = (blockIdx.x * 256 + threadIdx.x) * 4;
    int bh = idx4 >> 16;
    float gam = 1.0f - exp2f(-5.0f - (float)(bh & 7));
    float gC = powf(gam, 64.0f);
    size_t base = ((size_t)bh * NC << 16) + (idx4 & 65535);
    float4 s = {0.0f, 0.0f, 0.0f, 0.0f};
    for (int c = 0; c < NC; c++) {
        size_t p = base + ((size_t)c << 16);
        *(__half2*)(S + p)     = __floats2half2_rn(s.x, s.y);
        *(__half2*)(S + p + 2) = __floats2half2_rn(s.z, s.w);
        __half2 m01 = *(const __half2*)(M + p);
        __half2 m23 = *(const __half2*)(M + p + 2);
        float2 f01 = __half22float2(m01);
        float2 f23 = __half22float2(m23);
        s.x = gC * s.x + f01.x; s.y = gC * s.y + f01.y;
        s.z = gC * s.z + f23.x; s.w = gC * s.w + f23.y;
    }
}

// ---------------- retention pass C: per-chunk output (2-row tiling) --------
__global__ void __launch_bounds__(256) retention_out_kernel(const float* __restrict__ q,
                                                            const float* __restrict__ k,
                                                            const float* __restrict__ v,
                                                            const __half* __restrict__ S,
                                                            float* __restrict__ o) {
    __shared__ float Asm[64][65];
    __shared__ float t0[64][33];
    __shared__ float t1t[32][66];
    __shared__ float st[8][256];
    __shared__ float qs[8][64];
    const int chunk = blockIdx.x, bh = blockIdx.y;
    const int b = bh >> 3;
    const int tid = threadIdx.x;
    const size_t rowbase = ((size_t)b * TT + chunk * CK) * DD + (bh & 7) * DK;
    const int i2 = tid >> 3;
    const int eo = tid & 7;

    // ---- step 1: A = q2 k2^T ----
    {
        const int jg = eo * 8;
        unsigned long long accA[2][4];
        #pragma unroll
        for (int r = 0; r < 2; r++)
            #pragma unroll
            for (int p = 0; p < 4; p++) accA[r][p] = 0ull;
        for (int d0 = 0; d0 < 256; d0 += 32) {
            for (int l = tid; l < 2048; l += 256) {
                int r = l >> 5, c = l & 31;
                t0[r][c] = q[rowbase + (size_t)r * DD + d0 + c];
            }
            for (int l = tid; l < 2048; l += 256) {
                int dd = l & 31, jj = l >> 5;
                t1t[dd][jj] = k[rowbase + (size_t)jj * DD + d0 + dd];
            }
            __syncthreads();
            for (int dd = 0; dd < 32; dd++) {
                float q0 = t0[i2][dd], q1 = t0[i2 + 32][dd];
                unsigned long long qp0 = pk2(q0, q0), qp1 = pk2(q1, q1);
                const unsigned long long* kp = (const unsigned long long*)&t1t[dd][jg];
                #pragma unroll
                for (int p = 0; p < 4; p++) {
                    unsigned long long kv = kp[p];
                    fma2(accA[0][p], qp0, kv);
                    fma2(accA[1][p], qp1, kv);
                }
            }
            __syncthreads();
        }
        #pragma unroll
        for (int r = 0; r < 2; r++) {
            int i = i2 + 32 * r;
            #pragma unroll
            for (int p = 0; p < 4; p++) {
                float2 a = up2(accA[r][p]);
                int j0 = jg + 2 * p;
                Asm[i][j0]     = (i >= j0)     ? a.x : 0.0f;
                Asm[i][j0 + 1] = (i >= j0 + 1) ? a.y : 0.0f;
            }
        }
    }
    __syncthreads();

    // ---- step 2: o[i][e] ----
    unsigned long long acc[2][16];
    #pragma unroll
    for (int r = 0; r < 2; r++)
        #pragma unroll
        for (int m = 0; m < 16; m++) acc[r][m] = 0ull;

    // 2a: A @ v
    for (int j0 = 0; j0 < 64; j0 += 8) {
        for (int l = tid; l < 2048; l += 256) {
            int r = l >> 8, c = l & 255;
            st[r][c] = v[rowbase + (size_t)(j0 + r) * DD + c];
        }
        __syncthreads();
        #pragma unroll
        for (int jj = 0; jj < 8; jj++) {
            float a0 = Asm[i2][j0 + jj], a1 = Asm[i2 + 32][j0 + jj];
            unsigned long long ap0 = pk2(a0, a0), ap1 = pk2(a1, a1);
            const unsigned long long* vp = (const unsigned long long*)st[jj];
            #pragma unroll
            for (int m = 0; m < 16; m++) {
                unsigned long long sv = vp[eo + 8 * m];
                fma2(acc[0][m], ap0, sv);
                fma2(acc[1][m], ap1, sv);
            }
        }
        __syncthreads();
    }

    // 2b: + q2 @ S (S in fp16, converted on smem load)
    {
        const __half* Sb = S + (((size_t)bh * NC + chunk) << 16);
        for (int d0 = 0; d0 < 256; d0 += 8) {
            for (int l = tid; l < 1024; l += 256) {
                int r = l >> 7, c2 = (l & 127) * 2;
                __half2 hv = *(const __half2*)(Sb + (size_t)(d0 + r) * DV + c2);
                float2 fv = __half22float2(hv);
                st[r][c2] = fv.x; st[r][c2 + 1] = fv.y;
            }
            for (int l = tid; l < 512; l += 256) {
                int dd = l & 7, i = l >> 3;
                qs[dd][i] = q[rowbase + (size_t)i * DD + d0 + dd];
            }
            __syncthreads();
            #pragma unroll
            for (int dd = 0; dd < 8; dd++) {
                float q0 = qs[dd][i2], q1 = qs[dd][i2 + 32];
                unsigned long long qp0 = pk2(q0, q0), qp1 = pk2(q1, q1);
                const unsigned long long* sp = (const unsigned long long*)st[dd];
                #pragma unroll
                for (int m = 0; m < 16; m++) {
                    unsigned long long sv = sp[eo + 8 * m];
                    fma2(acc[0][m], qp0, sv);
                    fma2(acc[1][m], qp1, sv);
                }
            }
            __syncthreads();
        }
    }

    #pragma unroll
    for (int r = 0; r < 2; r++) {
        float* ob = o + rowbase + (size_t)(i2 + 32 * r) * DD;
        #pragma unroll
        for (int m = 0; m < 16; m++) {
            float2 rr = up2(acc[r][m]);
            int e = 2 * (eo + 8 * m);
            ob[e] = rr.x; ob[e + 1] = rr.y;
        }
    }
}

// ---------------- per-head rmsnorm(o)*silu(g) -> fp16 (g strided) ----------
__global__ void __launch_bounds__(256) gnorm_half_kernel(const float* __restrict__ o,
                                                         const float* __restrict__ g,
                                                         const float* __restrict__ w,
                                                         __half* __restrict__ hi) {
    const int row = blockIdx.x >> 3, hh = blockIdx.x & 7;
    const size_t base = (size_t)row * DD + hh * DV;
    const size_t gbase = (size_t)row * NQKVG + hh * DV;
    const int tid = threadIdx.x;
    float val = o[base + tid];
    float tot = block_sum_256(val * val);
    float rinv = rsqrtf(tot * (1.0f / (float)DV) + EPSV);
    float gv = g[gbase + tid];
    hi[base + tid] = __float2half_rn(val * rinv * w[tid] * gv * sigf(gv));
}

// ---------------- SwiGLU -> fp16 ----------------
__global__ void __launch_bounds__(256) swiglu_half_kernel(const float* __restrict__ gy,
                                                          __half* __restrict__ hi) {
    unsigned int idx2 = blockIdx.x * 256 + threadIdx.x;
    unsigned int row = idx2 / (INTER / 2);
    unsigned int c = (idx2 - row * (INTER / 2)) * 2;
    size_t p = (size_t)row * (2 * INTER) + c;
    float g0 = gy[p],         g1 = gy[p + 1];
    float y0 = gy[p + INTER], y1 = gy[p + INTER + 1];
    float u0 = g0 * sigf(g0) * y0;
    float u1 = g1 * sigf(g1) * y1;
    size_t q = (size_t)row * INTER + c;
    *(__half2*)(hi + q) = __half2{__float2half_rn(u0), __float2half_rn(u1)};
}

// ---------------- launch ----------------
extern "C" void kernel_launch(void* const* d_in, const int* in_sizes, int n_in,
                              void* d_out, int out_size) {
    (void)in_sizes; (void)n_in; (void)out_size;
    const float* hidden      = (const float*)d_in[0];
    const float* attn_norm_w = (const float*)d_in[1];
    const float* Wq          = (const float*)d_in[2];
    const float* Wk          = (const float*)d_in[3];
    const float* Wv          = (const float*)d_in[4];
    const float* Wg          = (const float*)d_in[5];
    const float* Wo          = (const float*)d_in[6];
    const float* conv_wq     = (const float*)d_in[7];
    const float* conv_wk     = (const float*)d_in[8];
    const float* conv_wv     = (const float*)d_in[9];
    const float* gnorm_w     = (const float*)d_in[10];
    const float* mlp_norm_w  = (const float*)d_in[11];
    const float* W_gate      = (const float*)d_in[12];
    const float* W_down      = (const float*)d_in[13];
    float* out = (float*)d_out;

    float *pqkvg, *pq, *pk, *pv, *po, *ph, *pgy;
    __half *pM, *pS, *pah, *pbh;
    cudaGetSymbolAddress((void**)&pqkvg, g_qkvg);
    cudaGetSymbolAddress((void**)&pq,  g_q);
    cudaGetSymbolAddress((void**)&pk,  g_k);
    cudaGetSymbolAddress((void**)&pv,  g_v);
    cudaGetSymbolAddress((void**)&pM,  g_M);
    cudaGetSymbolAddress((void**)&pS,  g_S);
    cudaGetSymbolAddress((void**)&po,  g_o);
    cudaGetSymbolAddress((void**)&ph,  g_h);
    cudaGetSymbolAddress((void**)&pgy, g_gy);
    cudaGetSymbolAddress((void**)&pah, g_ah);
    cudaGetSymbolAddress((void**)&pbh, g_bh);

    cudaFuncSetAttribute(hgemm_kernel, cudaFuncAttributeMaxDynamicSharedMemorySize, HSMEM_TOTAL);

    const dim3 gQKVG(NQKVG / 128, NTOK / 128);        // 64 x 32
    const dim3 gD(DD / 128, NTOK / 128);              // 16 x 32
    const dim3 gGate((2 * INTER) / 128, NTOK / 128);  // 44 x 32
    const dim3 tD(DD / 32, DD / 32);
    const dim3 tGate((2 * INTER) / 32, DD / 32);
    const dim3 tDown(DD / 32, INTER / 32);

    // x = rmsnorm(hidden) -> fp16
    rmsnorm_half_kernel<<<NTOK, 256>>>(hidden, attn_norm_w, pah);

    // batched q|k|v|g projection (one N=8192 GEMM)
    conv_halfT_kernel<<<tD, 256>>>(Wq, pbh,                          DD, DD);
    conv_halfT_kernel<<<tD, 256>>>(Wk, pbh + (size_t)1 * DD * DD,    DD, DD);
    conv_halfT_kernel<<<tD, 256>>>(Wv, pbh + (size_t)2 * DD * DD,    DD, DD);
    conv_halfT_kernel<<<tD, 256>>>(Wg, pbh + (size_t)3 * DD * DD,    DD, DD);
    hgemm_kernel<<<gQKVG, 256, HSMEM_TOTAL>>>(pah, pbh, nullptr, pqkvg, NTOK, NQKVG, DD);

    // conv+silu (+rope + decay prefold for q,k)
    conv_silu_rope_kernel<<<(NTOK * HH * 128) / 256, 256>>>(pqkvg,      conv_wq, pq, 0.0625f,  1.0f);
    conv_silu_rope_kernel<<<(NTOK * HH * 128) / 256, 256>>>(pqkvg + DD, conv_wk, pk, 1.0f,    -1.0f);
    conv_silu_kernel<<<(NTOK * DD) / 256, 256>>>(pqkvg + 2 * DD, conv_wv, pv);

    chunk_kv_kernel<<<dim3(16, NC, BB * HH), 256>>>(pk, pv, pM);
    scan_state_kernel<<<(BB * HH * DK * DV / 4) / 256, 256>>>(pM, pS);
    retention_out_kernel<<<dim3(NC, BB * HH), 256>>>(pq, pk, pv, pS, po);

    // gated norm -> fp16 (g read from qkvg panel 3)
    gnorm_half_kernel<<<NTOK * HH, 256>>>(po, pqkvg + 3 * DD, gnorm_w, pah);

    // h = o2 @ Wo + hidden
    conv_halfT_kernel<<<tD, 256>>>(Wo, pbh, DD, DD);
    hgemm_kernel<<<gD, 256, HSMEM_TOTAL>>>(pah, pbh, hidden, ph, NTOK, DD, DD);

    // MLP
    rmsnorm_half_kernel<<<NTOK, 256>>>(ph, mlp_norm_w, pah);
    conv_halfT_kernel<<<tGate, 256>>>(W_gate, pbh, DD, 2 * INTER);
    hgemm_kernel<<<gGate, 256, HSMEM_TOTAL>>>(pah, pbh, nullptr, pgy, NTOK, 2 * INTER, DD);

    swiglu_half_kernel<<<(NTOK * INTER / 2) / 256, 256>>>(pgy, pah);
    conv_halfT_kernel<<<tDown, 256>>>(W_down, pbh, INTER, DD);
    hgemm_kernel<<<gD, 256, HSMEM_TOTAL>>>(pah, pbh, ph, out, NTOK, DD, INTER);
}

// round 16
// speedup vs baseline: 1.1475x; 1.0762x over previous
#include <cuda_runtime.h>
#include <cuda_bf16.h>
#include <cuda_fp16.h>
#include <math.h>
#include <stdint.h>

// ---------------- problem constants ----------------
#define BB 2
#define TT 2048
#define DD 2048
#define HH 8
#define DK 256
#define DV 256
#define NC 32          // T / CHUNK
#define CK 64          // chunk size
#define INTER 2816
#define EPSV 1e-5f
#define NQKVG 8192     // batched projection width

// ---------------- scratch (device globals; no allocations allowed) ----------
#define NTOK (BB*TT)               // 4096
__device__ float g_qkvg[NTOK*NQKVG];   // batched q|k|v|g projections
__device__ float g_q  [NTOK*DD];       // q2 (prescaled)
__device__ float g_k  [NTOK*DD];       // k2 (prescaled)
__device__ float g_v  [NTOK*DD];
__device__ float g_M  [BB*HH*NC*DK*DV];   // fp32 chunk KV summaries
__device__ float g_S  [BB*HH*NC*DK*DV];   // fp32 per-chunk states
__device__ float g_o  [NTOK*DD];
__device__ float g_h  [NTOK*DD];
__device__ float g_gy [NTOK*2*INTER];

// fp16 buffers (A: activations, B: transposed weights)
#define AMAX (NTOK*INTER)
#define BMAX (4*DD*DD)
__device__ __align__(256) __half g_ah[AMAX];
__device__ __align__(256) __half g_bh[BMAX];

// ---------------- f32x2 packed-FMA helpers ----------------
__device__ __forceinline__ unsigned long long pk2(float lo, float hi) {
    unsigned long long r;
    asm("mov.b64 %0, {%1, %2};" : "=l"(r) : "f"(lo), "f"(hi));
    return r;
}
__device__ __forceinline__ void fma2(unsigned long long& c, unsigned long long a, unsigned long long b) {
    asm("fma.rn.f32x2 %0, %1, %2, %0;" : "+l"(c) : "l"(a), "l"(b));
}
__device__ __forceinline__ float2 up2(unsigned long long v) {
    float2 r;
    asm("mov.b64 {%0, %1}, %2;" : "=f"(r.x), "=f"(r.y) : "l"(v));
    return r;
}

__device__ __forceinline__ float sigf(float x) { return 1.0f / (1.0f + expf(-x)); }

__device__ __forceinline__ float block_sum_256(float v) {
    __shared__ float red[8];
    __shared__ float tot;
    #pragma unroll
    for (int o = 16; o; o >>= 1) v += __shfl_xor_sync(0xffffffffu, v, o);
    int tid = threadIdx.x;
    if ((tid & 31) == 0) red[tid >> 5] = v;
    __syncthreads();
    if (tid == 0) {
        float t = red[0];
        #pragma unroll
        for (int i = 1; i < 8; i++) t += red[i];
        tot = t;
    }
    __syncthreads();
    return tot;
}

// ================= baseline-PTX MMA helpers =================
__device__ __forceinline__ uint32_t smem_u32(const void* p) {
    uint32_t a;
    asm("{ .reg .u64 t; cvta.to.shared.u64 t, %1; cvt.u32.u64 %0, t; }" : "=r"(a) : "l"(p));
    return a;
}
#define SWZ64(off) ((off) ^ ((((unsigned)(off)) >> 3) & 0x30u))

__device__ __forceinline__ void ldsm4(uint32_t* r, uint32_t addr) {
    asm volatile("ldmatrix.sync.aligned.m8n8.x4.shared.b16 {%0,%1,%2,%3}, [%4];"
                 : "=r"(r[0]), "=r"(r[1]), "=r"(r[2]), "=r"(r[3]) : "r"(addr));
}
__device__ __forceinline__ void mma16816(float* d, const uint32_t* a, const uint32_t* b) {
    asm volatile(
        "mma.sync.aligned.m16n8k16.row.col.f32.f16.f16.f32 "
        "{%0,%1,%2,%3}, {%4,%5,%6,%7}, {%8,%9}, {%0,%1,%2,%3};"
        : "+f"(d[0]), "+f"(d[1]), "+f"(d[2]), "+f"(d[3])
        : "r"(a[0]), "r"(a[1]), "r"(a[2]), "r"(a[3]), "r"(b[0]), "r"(b[1]));
}
__device__ __forceinline__ void cpasync16(uint32_t dst, const void* src) {
    asm volatile("cp.async.cg.shared.global [%0], [%1], 16;" :: "r"(dst), "l"(src));
}

// ================= conversion / fused elementwise kernels =================

__global__ void __launch_bounds__(256) rmsnorm_half_kernel(const float* __restrict__ in,
                                                           const float* __restrict__ w,
                                                           __half* __restrict__ hi) {
    const size_t base = (size_t)blockIdx.x * DD;
    const int tid = threadIdx.x;
    float4 v0 = *(const float4*)(in + base + tid * 4);
    float4 v1 = *(const float4*)(in + base + 1024 + tid * 4);
    float ss = v0.x*v0.x + v0.y*v0.y + v0.z*v0.z + v0.w*v0.w
             + v1.x*v1.x + v1.y*v1.y + v1.z*v1.z + v1.w*v1.w;
    float tot = block_sum_256(ss);
    float rinv = rsqrtf(tot * (1.0f / (float)DD) + EPSV);
    float4 w0 = *(const float4*)(w + tid * 4);
    float4 w1 = *(const float4*)(w + 1024 + tid * 4);
    size_t o0 = base + tid * 4, o1 = base + 1024 + tid * 4;
    *(__half2*)(hi + o0)     = __half2{__float2half_rn(v0.x*rinv*w0.x), __float2half_rn(v0.y*rinv*w0.y)};
    *(__half2*)(hi + o0 + 2) = __half2{__float2half_rn(v0.z*rinv*w0.z), __float2half_rn(v0.w*rinv*w0.w)};
    *(__half2*)(hi + o1)     = __half2{__float2half_rn(v1.x*rinv*w1.x), __float2half_rn(v1.y*rinv*w1.y)};
    *(__half2*)(hi + o1 + 2) = __half2{__float2half_rn(v1.z*rinv*w1.z), __float2half_rn(v1.w*rinv*w1.w)};
}

// W[K][N] fp32 -> Bt[N][K] fp16 (transpose). 32x32 tiles.
__global__ void __launch_bounds__(256) conv_halfT_kernel(const float* __restrict__ W,
                                                         __half* __restrict__ hi,
                                                         int K, int N) {
    __shared__ float sh[32][33];
    const int n0 = blockIdx.x * 32, k0 = blockIdx.y * 32;
    const int tid = threadIdx.x;
    {
        int r = tid >> 3, c4 = (tid & 7) * 4;
        float4 v = *(const float4*)(W + (size_t)(k0 + r) * N + n0 + c4);
        sh[r][c4] = v.x; sh[r][c4 + 1] = v.y; sh[r][c4 + 2] = v.z; sh[r][c4 + 3] = v.w;
    }
    __syncthreads();
    {
        int nr = tid >> 3, kc4 = (tid & 7) * 4;
        __half h0 = __float2half_rn(sh[kc4][nr]);
        __half h1 = __float2half_rn(sh[kc4 + 1][nr]);
        __half h2 = __float2half_rn(sh[kc4 + 2][nr]);
        __half h3 = __float2half_rn(sh[kc4 + 3][nr]);
        size_t off = (size_t)(n0 + nr) * K + k0 + kc4;
        *(__half2*)(hi + off)     = __half2{h0, h1};
        *(__half2*)(hi + off + 2) = __half2{h2, h3};
    }
}

// 4 DxD weights transposed in one launch (z = weight index)
__global__ void __launch_bounds__(256) conv_halfT4_kernel(const float* __restrict__ W0,
                                                          const float* __restrict__ W1,
                                                          const float* __restrict__ W2,
                                                          const float* __restrict__ W3,
                                                          __half* __restrict__ hi) {
    __shared__ float sh[32][33];
    const int n0 = blockIdx.x * 32, k0 = blockIdx.y * 32;
    const int z = blockIdx.z;
    const float* W = (z == 0) ? W0 : (z == 1) ? W1 : (z == 2) ? W2 : W3;
    __half* out = hi + (size_t)z * DD * DD;
    const int tid = threadIdx.x;
    {
        int r = tid >> 3, c4 = (tid & 7) * 4;
        float4 v = *(const float4*)(W + (size_t)(k0 + r) * DD + n0 + c4);
        sh[r][c4] = v.x; sh[r][c4 + 1] = v.y; sh[r][c4 + 2] = v.z; sh[r][c4 + 3] = v.w;
    }
    __syncthreads();
    {
        int nr = tid >> 3, kc4 = (tid & 7) * 4;
        __half h0 = __float2half_rn(sh[kc4][nr]);
        __half h1 = __float2half_rn(sh[kc4 + 1][nr]);
        __half h2 = __float2half_rn(sh[kc4 + 2][nr]);
        __half h3 = __float2half_rn(sh[kc4 + 3][nr]);
        size_t off = (size_t)(n0 + nr) * DD + k0 + kc4;
        *(__half2*)(out + off)     = __half2{h0, h1};
        *(__half2*)(out + off + 2) = __half2{h2, h3};
    }
}

// ================= HMMA fp16 1-pass GEMM (R13 config: 128x128, 2 CTA/SM) ===
#define HSTAGE 16384
#define HSMEM_TOTAL (4*HSTAGE)

__global__ void __launch_bounds__(256, 2) hgemm_kernel(const __half* __restrict__ Ah,
                                                       const __half* __restrict__ Bh,
                                                       const float* __restrict__ addsrc,
                                                       float* __restrict__ C,
                                                       int M, int N, int K) {
    extern __shared__ char smem[];
    const uint32_t sb = smem_u32(smem);
    const int tid = threadIdx.x;
    const int lane = tid & 31, wid = tid >> 5;
    const int bm = blockIdx.y * 128, bn = blockIdx.x * 128;
    const int Ks = K >> 5;

    const int wm = wid & 3, wn = wid >> 2;
    const int m0 = wm * 32, nb = wn * 64;

    float acc[2][8][4];
    #pragma unroll
    for (int a = 0; a < 2; a++)
        #pragma unroll
        for (int b = 0; b < 8; b++)
            #pragma unroll
            for (int c = 0; c < 4; c++) acc[a][b][c] = 0.0f;

    const int lrow = tid >> 2, lch = tid & 3;

    auto load_step = [&](int s, int stage) {
        const int k0 = s << 5;
        const uint32_t so0 = SWZ64(lrow * 64 + lch * 16);
        const uint32_t so1 = SWZ64((lrow + 64) * 64 + lch * 16);
        {
            const __half* src = Ah + (size_t)bm * K + k0 + lch * 8;
            const uint32_t dbase = sb + stage * HSTAGE;
            cpasync16(dbase + so0, src + (size_t)lrow * K);
            cpasync16(dbase + so1, src + (size_t)(lrow + 64) * K);
        }
        {
            const __half* src = Bh + (size_t)bn * K + k0 + lch * 8;
            const uint32_t dbase = sb + stage * HSTAGE + 8192;
            cpasync16(dbase + so0, src + (size_t)lrow * K);
            cpasync16(dbase + so1, src + (size_t)(lrow + 64) * K);
        }
        asm volatile("cp.async.commit_group;" ::: "memory");
    };

    load_step(0, 0);
    load_step(1, 1);
    load_step(2, 2);

    const int arow = lane & 15;
    const int akb  = (lane >> 4) << 4;
    const int brow = ((lane >> 4) << 3) + (lane & 7);
    const int bkb  = ((lane >> 3) & 1) << 4;

    for (int s = 0; s < Ks; s++) {
        const int stage = s & 3;
        const int rem = Ks - 1 - s;
        if (rem >= 2)      asm volatile("cp.async.wait_group 2;" ::: "memory");
        else if (rem == 1) asm volatile("cp.async.wait_group 1;" ::: "memory");
        else               asm volatile("cp.async.wait_group 0;" ::: "memory");
        __syncthreads();
        if (s + 3 < Ks) load_step(s + 3, (s + 3) & 3);
        const uint32_t base = sb + stage * HSTAGE;
        #pragma unroll
        for (int kk = 0; kk < 2; kk++) {
            uint32_t ah[2][4], bb[4][4];
            #pragma unroll
            for (int mi = 0; mi < 2; mi++) {
                uint32_t aoff = SWZ64((m0 + mi * 16 + arow) * 64 + kk * 32 + akb);
                ldsm4(ah[mi], base + aoff);
            }
            #pragma unroll
            for (int nj = 0; nj < 4; nj++)
                ldsm4(bb[nj], base + 8192 + SWZ64((nb + nj * 16 + brow) * 64 + kk * 32 + bkb));
            #pragma unroll
            for (int mi = 0; mi < 2; mi++)
                #pragma unroll
                for (int nt = 0; nt < 8; nt++)
                    mma16816(acc[mi][nt], ah[mi], &bb[nt >> 1][(nt & 1) * 2]);
        }
    }

    #pragma unroll
    for (int mi = 0; mi < 2; mi++) {
        #pragma unroll
        for (int nt = 0; nt < 8; nt++) {
            int row = bm + m0 + mi * 16 + (lane >> 2);
            int col = bn + nb + nt * 8 + (lane & 3) * 2;
            size_t off0 = (size_t)row * N + col;
            size_t off1 = off0 + (size_t)8 * N;
            float2 v0 = { acc[mi][nt][0], acc[mi][nt][1] };
            float2 v1 = { acc[mi][nt][2], acc[mi][nt][3] };
            if (addsrc) {
                float2 a0 = *(const float2*)(addsrc + off0);
                float2 a1 = *(const float2*)(addsrc + off1);
                v0.x += a0.x; v0.y += a0.y; v1.x += a1.x; v1.y += a1.y;
            }
            *(float2*)(C + off0) = v0;
            *(float2*)(C + off1) = v1;
        }
    }
}

// ---------------- causal conv(K=4)+SiLU, strided input ----------------
__device__ __forceinline__ float conv_at(const float* __restrict__ x, size_t idx,
                                         int t, const float* __restrict__ w, int d,
                                         int stride) {
    float acc = x[idx] * w[d * 4 + 3];
    if (t >= 1) acc += x[idx - stride]     * w[d * 4 + 2];
    if (t >= 2) acc += x[idx - 2 * stride] * w[d * 4 + 1];
    if (t >= 3) acc += x[idx - 3 * stride] * w[d * 4 + 0];
    return acc;
}

__global__ void __launch_bounds__(256) conv_silu_kernel(const float* __restrict__ x,
                                                        const float* __restrict__ w,
                                                        float* __restrict__ out) {
    unsigned int idx = blockIdx.x * 256 + threadIdx.x;
    int d = (int)(idx & (DD - 1));
    int row = (int)(idx >> 11);
    int t = row & (TT - 1);
    size_t src = (size_t)row * NQKVG + d;
    float acc = conv_at(x, src, t, w, d, NQKVG);
    out[idx] = acc * sigf(acc);
}

// fused conv+SiLU+RoPE with per-token decay prefold
__global__ void __launch_bounds__(256) conv_silu_rope_kernel(const float* __restrict__ x,
                                                             const float* __restrict__ w,
                                                             float* __restrict__ out,
                                                             float base, float sign) {
    int idx = blockIdx.x * 256 + threadIdx.x;
    int j = idx & 127;
    int h = (idx >> 7) & 7;
    int bt = idx >> 10;
    int t = bt & (TT - 1);
    int d1 = h * DK + j;
    int d2 = d1 + 128;
    size_t i1 = (size_t)bt * NQKVG + d1;
    size_t i2 = i1 + 128;
    float a1 = conv_at(x, i1, t, w, d1, NQKVG);
    float a2 = conv_at(x, i2, t, w, d2, NQKVG);
    a1 *= sigf(a1);
    a2 *= sigf(a2);
    float inv = powf(10000.0f, -(float)(2 * j) * (1.0f / 256.0f));
    float fr = (float)t * inv;
    float s, c;
    sincosf(fr, &s, &c);
    float gam = 1.0f - exp2f(-5.0f - (float)h);
    float scale = base * powf(gam, sign * (float)((t & 63) + 1));
    size_t o1 = (size_t)bt * DD + d1;
    out[o1]       = (a1 * c - a2 * s) * scale;
    out[o1 + 128] = (a2 * c + a1 * s) * scale;
}

// ---------------- retention pass A: per-chunk KV summary (128x128 tiles) ---
// k here is k2 (prescaled by gam^-(j+1)); decay becomes constant gam^64.
// Block computes a 128(d) x 128(e) tile; grid (4, NC, BH).
#define CKV_STRIDE 132
#define CKV_SMEM (2 * 64 * CKV_STRIDE * 4)   // 67584 bytes

__global__ void __launch_bounds__(256) chunk_kv_kernel(const float* __restrict__ k,
                                                       const float* __restrict__ v,
                                                       float* __restrict__ M) {
    extern __shared__ float cs[];
    float* kt = cs;                       // [64][CKV_STRIDE]
    float* vt = cs + 64 * CKV_STRIDE;     // [64][CKV_STRIDE]
    const int tile = blockIdx.x;
    const int d0 = (tile >> 1) * 128, e0 = (tile & 1) * 128;
    const int chunk = blockIdx.y, bh = blockIdx.z;
    const int b = bh >> 3, h = bh & 7;
    const float gam = 1.0f - exp2f(-5.0f - (float)h);
    const float gC64 = powf(gam, 64.0f);
    const int tid = threadIdx.x;
    const size_t rowbase = ((size_t)b * TT + chunk * CK) * DD + h * DK;

    // load 64x128 k (scaled) and v tiles
    for (int l = tid; l < 2048; l += 256) {
        int r = l >> 5, c4 = (l & 31) * 4;
        float4 kk = *(const float4*)(k + rowbase + (size_t)r * DD + d0 + c4);
        kk.x *= gC64; kk.y *= gC64; kk.z *= gC64; kk.w *= gC64;
        *(float4*)(kt + r * CKV_STRIDE + c4) = kk;
        float4 vv = *(const float4*)(v + rowbase + (size_t)r * DD + e0 + c4);
        *(float4*)(vt + r * CKV_STRIDE + c4) = vv;
    }
    __syncthreads();

    // each thread: d rows {dt*4..+3, 64+dt*4..+3}, e cols {et*4..+3, 64+et*4..+3}
    const int dt = tid >> 4, et = tid & 15;
    unsigned long long acc[8][4];
    #pragma unroll
    for (int r = 0; r < 8; r++)
        #pragma unroll
        for (int p = 0; p < 4; p++) acc[r][p] = 0ull;

    for (int j = 0; j < 64; j++) {
        const float* krow = kt + j * CKV_STRIDE;
        const float* vrow = vt + j * CKV_STRIDE;
        float4 k0 = *(const float4*)(krow + dt * 4);
        float4 k1 = *(const float4*)(krow + 64 + dt * 4);
        float4 v0 = *(const float4*)(vrow + et * 4);
        float4 v1 = *(const float4*)(vrow + 64 + et * 4);
        unsigned long long vp[4] = { pk2(v0.x, v0.y), pk2(v0.z, v0.w),
                                     pk2(v1.x, v1.y), pk2(v1.z, v1.w) };
        float kr[8] = { k0.x, k0.y, k0.z, k0.w, k1.x, k1.y, k1.z, k1.w };
        #pragma unroll
        for (int r = 0; r < 8; r++) {
            unsigned long long kp = pk2(kr[r], kr[r]);
            #pragma unroll
            for (int p = 0; p < 4; p++) fma2(acc[r][p], kp, vp[p]);
        }
    }

    size_t mbase = (((size_t)bh * NC + chunk) << 16);
    #pragma unroll
    for (int r = 0; r < 8; r++) {
        int d = (r < 4) ? (dt * 4 + r) : (64 + dt * 4 + r - 4);
        size_t pbase = mbase + (size_t)(d0 + d) * DV + e0;
        float2 a0 = up2(acc[r][0]), a1 = up2(acc[r][1]);
        float2 a2 = up2(acc[r][2]), a3 = up2(acc[r][3]);
        float4 w0 = { a0.x, a0.y, a1.x, a1.y };
        float4 w1 = { a2.x, a2.y, a3.x, a3.y };
        *(float4*)(M + pbase + et * 4)      = w0;
        *(float4*)(M + pbase + 64 + et * 4) = w1;
    }
}

// ---------------- retention pass B: state scan (float4, fp32) ----------------
__global__ void __launch_bounds__(256) scan_state_kernel(const float* __restrict__ M,
                                                         float* __restrict__ S) {
    int idx4 = (blockIdx.x * 256 + threadIdx.x) * 4;
    int bh = idx4 >> 16;
    float gam = 1.0f - exp2f(-5.0f - (float)(bh & 7));
    float gC = powf(gam, 64.0f);
    size_t base = ((size_t)bh * NC << 16) + (idx4 & 65535);
    float4 s = {0.0f, 0.0f, 0.0f, 0.0f};
    for (int c = 0; c < NC; c++) {
        size_t p = base + ((size_t)c << 16);
        *(float4*)(S + p) = s;
        float4 m = *(const float4*)(M + p);
        s.x = gC * s.x + m.x; s.y = gC * s.y + m.y;
        s.z = gC * s.z + m.z; s.w = gC * s.w + m.w;
    }
}

// ---------------- retention pass C: per-chunk output (2-row tiling) --------
__global__ void __launch_bounds__(256) retention_out_kernel(const float* __restrict__ q,
                                                            const float* __restrict__ k,
                                                            const float* __restrict__ v,
                                                            const float* __restrict__ S,
                                                            float* __restrict__ o) {
    __shared__ float Asm[64][65];
    __shared__ float t0[64][33];
    __shared__ float t1t[32][66];
    __shared__ float st[8][256];
    __shared__ float qs[8][64];
    const int chunk = blockIdx.x, bh = blockIdx.y;
    const int b = bh >> 3;
    const int tid = threadIdx.x;
    const size_t rowbase = ((size_t)b * TT + chunk * CK) * DD + (bh & 7) * DK;
    const int i2 = tid >> 3;
    const int eo = tid & 7;

    // ---- step 1: A = q2 k2^T ----
    {
        const int jg = eo * 8;
        unsigned long long accA[2][4];
        #pragma unroll
        for (int r = 0; r < 2; r++)
            #pragma unroll
            for (int p = 0; p < 4; p++) accA[r][p] = 0ull;
        for (int d0 = 0; d0 < 256; d0 += 32) {
            for (int l = tid; l < 2048; l += 256) {
                int r = l >> 5, c = l & 31;
                t0[r][c] = q[rowbase + (size_t)r * DD + d0 + c];
            }
            for (int l = tid; l < 2048; l += 256) {
                int dd = l & 31, jj = l >> 5;
                t1t[dd][jj] = k[rowbase + (size_t)jj * DD + d0 + dd];
            }
            __syncthreads();
            for (int dd = 0; dd < 32; dd++) {
                float q0 = t0[i2][dd], q1 = t0[i2 + 32][dd];
                unsigned long long qp0 = pk2(q0, q0), qp1 = pk2(q1, q1);
                const unsigned long long* kp = (const unsigned long long*)&t1t[dd][jg];
                #pragma unroll
                for (int p = 0; p < 4; p++) {
                    unsigned long long kv = kp[p];
                    fma2(accA[0][p], qp0, kv);
                    fma2(accA[1][p], qp1, kv);
                }
            }
            __syncthreads();
        }
        #pragma unroll
        for (int r = 0; r < 2; r++) {
            int i = i2 + 32 * r;
            #pragma unroll
            for (int p = 0; p < 4; p++) {
                float2 a = up2(accA[r][p]);
                int j0 = jg + 2 * p;
                Asm[i][j0]     = (i >= j0)     ? a.x : 0.0f;
                Asm[i][j0 + 1] = (i >= j0 + 1) ? a.y : 0.0f;
            }
        }
    }
    __syncthreads();

    // ---- step 2: o[i][e] ----
    unsigned long long acc[2][16];
    #pragma unroll
    for (int r = 0; r < 2; r++)
        #pragma unroll
        for (int m = 0; m < 16; m++) acc[r][m] = 0ull;

    // 2a: A @ v
    for (int j0 = 0; j0 < 64; j0 += 8) {
        for (int l = tid; l < 2048; l += 256) {
            int r = l >> 8, c = l & 255;
            st[r][c] = v[rowbase + (size_t)(j0 + r) * DD + c];
        }
        __syncthreads();
        #pragma unroll
        for (int jj = 0; jj < 8; jj++) {
            float a0 = Asm[i2][j0 + jj], a1 = Asm[i2 + 32][j0 + jj];
            unsigned long long ap0 = pk2(a0, a0), ap1 = pk2(a1, a1);
            const unsigned long long* vp = (const unsigned long long*)st[jj];
            #pragma unroll
            for (int m = 0; m < 16; m++) {
                unsigned long long sv = vp[eo + 8 * m];
                fma2(acc[0][m], ap0, sv);
                fma2(acc[1][m], ap1, sv);
            }
        }
        __syncthreads();
    }

    // 2b: + q2 @ S
    {
        const float* Sb = S + (((size_t)bh * NC + chunk) << 16);
        for (int d0 = 0; d0 < 256; d0 += 8) {
            for (int l = tid; l < 2048; l += 256) {
                int r = l >> 8, c = l & 255;
                st[r][c] = Sb[(size_t)(d0 + r) * DV + c];
            }
            for (int l = tid; l < 512; l += 256) {
                int dd = l & 7, i = l >> 3;
                qs[dd][i] = q[rowbase + (size_t)i * DD + d0 + dd];
            }
            __syncthreads();
            #pragma unroll
            for (int dd = 0; dd < 8; dd++) {
                float q0 = qs[dd][i2], q1 = qs[dd][i2 + 32];
                unsigned long long qp0 = pk2(q0, q0), qp1 = pk2(q1, q1);
                const unsigned long long* sp = (const unsigned long long*)st[dd];
                #pragma unroll
                for (int m = 0; m < 16; m++) {
                    unsigned long long sv = sp[eo + 8 * m];
                    fma2(acc[0][m], qp0, sv);
                    fma2(acc[1][m], qp1, sv);
                }
            }
            __syncthreads();
        }
    }

    #pragma unroll
    for (int r = 0; r < 2; r++) {
        float* ob = o + rowbase + (size_t)(i2 + 32 * r) * DD;
        #pragma unroll
        for (int m = 0; m < 16; m++) {
            float2 rr = up2(acc[r][m]);
            int e = 2 * (eo + 8 * m);
            ob[e] = rr.x; ob[e + 1] = rr.y;
        }
    }
}

// ---------------- per-head rmsnorm(o)*silu(g) -> fp16 (g strided) ----------
__global__ void __launch_bounds__(256) gnorm_half_kernel(const float* __restrict__ o,
                                                         const float* __restrict__ g,
                                                         const float* __restrict__ w,
                                                         __half* __restrict__ hi) {
    const int row = blockIdx.x >> 3, hh = blockIdx.x & 7;
    const size_t base = (size_t)row * DD + hh * DV;
    const size_t gbase = (size_t)row * NQKVG + hh * DV;
    const int tid = threadIdx.x;
    float val = o[base + tid];
    float tot = block_sum_256(val * val);
    float rinv = rsqrtf(tot * (1.0f / (float)DV) + EPSV);
    float gv = g[gbase + tid];
    hi[base + tid] = __float2half_rn(val * rinv * w[tid] * gv * sigf(gv));
}

// ---------------- SwiGLU -> fp16 ----------------
__global__ void __launch_bounds__(256) swiglu_half_kernel(const float* __restrict__ gy,
                                                          __half* __restrict__ hi) {
    unsigned int idx2 = blockIdx.x * 256 + threadIdx.x;
    unsigned int row = idx2 / (INTER / 2);
    unsigned int c = (idx2 - row * (INTER / 2)) * 2;
    size_t p = (size_t)row * (2 * INTER) + c;
    float g0 = gy[p],         g1 = gy[p + 1];
    float y0 = gy[p + INTER], y1 = gy[p + INTER + 1];
    float u0 = g0 * sigf(g0) * y0;
    float u1 = g1 * sigf(g1) * y1;
    size_t q = (size_t)row * INTER + c;
    *(__half2*)(hi + q) = __half2{__float2half_rn(u0), __float2half_rn(u1)};
}

// ---------------- launch ----------------
extern "C" void kernel_launch(void* const* d_in, const int* in_sizes, int n_in,
                              void* d_out, int out_size) {
    (void)in_sizes; (void)n_in; (void)out_size;
    const float* hidden      = (const float*)d_in[0];
    const float* attn_norm_w = (const float*)d_in[1];
    const float* Wq          = (const float*)d_in[2];
    const float* Wk          = (const float*)d_in[3];
    const float* Wv          = (const float*)d_in[4];
    const float* Wg          = (const float*)d_in[5];
    const float* Wo          = (const float*)d_in[6];
    const float* conv_wq     = (const float*)d_in[7];
    const float* conv_wk     = (const float*)d_in[8];
    const float* conv_wv     = (const float*)d_in[9];
    const float* gnorm_w     = (const float*)d_in[10];
    const float* mlp_norm_w  = (const float*)d_in[11];
    const float* W_gate      = (const float*)d_in[12];
    const float* W_down      = (const float*)d_in[13];
    float* out = (float*)d_out;

    float *pqkvg, *pq, *pk, *pv, *pM, *pS, *po, *ph, *pgy;
    __half *pah, *pbh;
    cudaGetSymbolAddress((void**)&pqkvg, g_qkvg);
    cudaGetSymbolAddress((void**)&pq,  g_q);
    cudaGetSymbolAddress((void**)&pk,  g_k);
    cudaGetSymbolAddress((void**)&pv,  g_v);
    cudaGetSymbolAddress((void**)&pM,  g_M);
    cudaGetSymbolAddress((void**)&pS,  g_S);
    cudaGetSymbolAddress((void**)&po,  g_o);
    cudaGetSymbolAddress((void**)&ph,  g_h);
    cudaGetSymbolAddress((void**)&pgy, g_gy);
    cudaGetSymbolAddress((void**)&pah, g_ah);
    cudaGetSymbolAddress((void**)&pbh, g_bh);

    cudaFuncSetAttribute(hgemm_kernel, cudaFuncAttributeMaxDynamicSharedMemorySize, HSMEM_TOTAL);
    cudaFuncSetAttribute(chunk_kv_kernel, cudaFuncAttributeMaxDynamicSharedMemorySize, CKV_SMEM);

    const dim3 gQKVG(NQKVG / 128, NTOK / 128);        // 64 x 32
    const dim3 gD(DD / 128, NTOK / 128);              // 16 x 32
    const dim3 gGate((2 * INTER) / 128, NTOK / 128);  // 44 x 32
    const dim3 tD(DD / 32, DD / 32);
    const dim3 tD4(DD / 32, DD / 32, 4);
    const dim3 tGate((2 * INTER) / 32, DD / 32);
    const dim3 tDown(DD / 32, INTER / 32);

    // x = rmsnorm(hidden) -> fp16
    rmsnorm_half_kernel<<<NTOK, 256>>>(hidden, attn_norm_w, pah);

    // batched q|k|v|g projection (one N=8192 GEMM), weights transposed in 1 launch
    conv_halfT4_kernel<<<tD4, 256>>>(Wq, Wk, Wv, Wg, pbh);
    hgemm_kernel<<<gQKVG, 256, HSMEM_TOTAL>>>(pah, pbh, nullptr, pqkvg, NTOK, NQKVG, DD);

    // conv+silu (+rope + decay prefold for q,k)
    conv_silu_rope_kernel<<<(NTOK * HH * 128) / 256, 256>>>(pqkvg,      conv_wq, pq, 0.0625f,  1.0f);
    conv_silu_rope_kernel<<<(NTOK * HH * 128) / 256, 256>>>(pqkvg + DD, conv_wk, pk, 1.0f,    -1.0f);
    conv_silu_kernel<<<(NTOK * DD) / 256, 256>>>(pqkvg + 2 * DD, conv_wv, pv);

    chunk_kv_kernel<<<dim3(4, NC, BB * HH), 256, CKV_SMEM>>>(pk, pv, pM);
    scan_state_kernel<<<(BB * HH * DK * DV / 4) / 256, 256>>>(pM, pS);
    retention_out_kernel<<<dim3(NC, BB * HH), 256>>>(pq, pk, pv, pS, po);

    // gated norm -> fp16 (g read from qkvg panel 3)
    gnorm_half_kernel<<<NTOK * HH, 256>>>(po, pqkvg + 3 * DD, gnorm_w, pah);

    // h = o2 @ Wo + hidden
    conv_halfT_kernel<<<tD, 256>>>(Wo, pbh, DD, DD);
    hgemm_kernel<<<gD, 256, HSMEM_TOTAL>>>(pah, pbh, hidden, ph, NTOK, DD, DD);

    // MLP
    rmsnorm_half_kernel<<<NTOK, 256>>>(ph, mlp_norm_w, pah);
    conv_halfT_kernel<<<tGate, 256>>>(W_gate, pbh, DD, 2 * INTER);
    hgemm_kernel<<<gGate, 256, HSMEM_TOTAL>>>(pah, pbh, nullptr, pgy, NTOK, 2 * INTER, DD);

    swiglu_half_kernel<<<(NTOK * INTER / 2) / 256, 256>>>(pgy, pah);
    conv_halfT_kernel<<<tDown, 256>>>(W_down, pbh, INTER, DD);
    hgemm_kernel<<<gD, 256, HSMEM_TOTAL>>>(pah, pbh, ph, out, NTOK, DD, INTER);
}